// round 16
// baseline (speedup 1.0000x reference)
#include <cuda_runtime.h>
#include <cstdint>

#define BATCH 8
#define T_FULL 2048
#define C_DIM 1024
#define H_DIM 64
#define TA 1024
#define TB 1024
#define R_MERGE 512
#define RB (R_MERGE*BATCH)   /* 4096 */
#define NROWS (BATCH*TA)     /* 8192 */
#define X_ELEMS (BATCH*T_FULL*C_DIM)  /* 16777216 */

typedef unsigned long long u64;

// ---------------- scratch (__device__ globals; zero-initialized .bss) ----------------
__device__ u64 g_pack[NROWS];                  // (flip(max)<<32)|(1023-argmax); reset by k_plan
__device__ int g_table[BATCH*T_FULL];
__device__ int g_dstoff[NROWS];
__device__ int g_dstdeg[NROWS];
__device__ int g_dstlist[NROWS];               // per-batch segmented: batch b owns [b*1024, b*1024+mb)
__device__ unsigned g_thr, g_kprime;
__device__ unsigned g_eqbase[BATCH];
// normalized-b, duplicated (v,v) f32x2, chunked: [b][chunk32][k32][j64]
__device__ __align__(16) u64 g_bd[BATCH*32*32*64];   // 4 MB
__device__ float g_ainv[NROWS];                // 1/||a_row||

__device__ __forceinline__ unsigned fflip(float f) {
    unsigned u = __float_as_uint(f);
    return (u & 0x80000000u) ? ~u : (u | 0x80000000u);
}
__device__ __forceinline__ u64 packf2(float lo, float hi) {
    u64 r; asm("mov.b64 %0, {%1,%2};" : "=l"(r) : "f"(lo), "f"(hi)); return r;
}
#define FMA2(acc, av, bv) asm("fma.rn.f32x2 %0, %1, %2, %0;" : "+l"(acc) : "l"(av), "l"(bv))

// ---------------- prep: normalize b tokens (dup layout) + a-row inverse norms ----------------
__global__ void __launch_bounds__(256) k_prep(const float* __restrict__ metric) {
    __shared__ float st[64][65];
    int jt = blockIdx.x;          // 0..15 (64-token tiles)
    int b  = blockIdx.y;
    int tid = threadIdx.x, lane = tid & 31, w = tid >> 5;

    for (int r = w*8; r < w*8 + 8; r++) {
        int row = jt*64 + r;
        const float* m = metric + ((size_t)(b*T_FULL + 2*row))*H_DIM;
        float v0 = m[lane], v1 = m[lane+32];
        float ss = v0*v0 + v1*v1;
        #pragma unroll
        for (int o = 16; o; o >>= 1) ss += __shfl_xor_sync(0xffffffffu, ss, o);
        if (lane == 0) g_ainv[b*TA + row] = 1.0f / sqrtf(ss);
    }

    for (int idx = tid; idx < 64*64; idx += 256) {
        int t = idx >> 6, k = idx & 63;
        st[t][k] = metric[((size_t)(b*T_FULL + 2*(jt*64 + t) + 1))*H_DIM + k];
    }
    __syncthreads();
    for (int t = w*8; t < w*8 + 8; t++) {
        float v0 = st[t][lane], v1 = st[t][lane+32];
        float ss = v0*v0 + v1*v1;
        #pragma unroll
        for (int o = 16; o; o >>= 1) ss += __shfl_xor_sync(0xffffffffu, ss, o);
        float inv = 1.0f / sqrtf(ss);
        st[t][lane] = v0*inv; st[t][lane+32] = v1*inv;
    }
    __syncthreads();
    for (int idx = tid; idx < 4096; idx += 256) {
        int kc = idx >> 11, k32 = (idx >> 6) & 31, jl = idx & 63;
        float v = st[jl][kc*32 + k32];
        g_bd[(((size_t)(b*32 + jt*2 + kc))*32 + k32)*64 + jl] = packf2(v, v);
    }
}

// ---------------- scores: 16 rows/warp x 64 j; j split in 4 for occupancy ----------------
__global__ void __launch_bounds__(128) k_scores(const float* __restrict__ metric) {
    __shared__ __align__(16) unsigned char smem_raw[49152];
    u64* sa   = (u64*)smem_raw;                        // [64k][32rp] 16KB
    u64* sbuf = (u64*)(smem_raw + 16384);              // 2 x 16KB b chunks
    float (*staged)[65] = (float(*)[65])(smem_raw + 16384);  // prologue only

    int rowblk = blockIdx.x;     // 0..15 (64 rows)
    int jq     = blockIdx.y;     // 0..3 (256-j quarter)
    int b      = blockIdx.z;     // 0..7
    int tid = threadIdx.x, l = tid & 31, w = tid >> 5;

    for (int idx = tid; idx < 64*64; idx += 128) {
        int rl = idx >> 6, k = idx & 63;
        staged[rl][k] = metric[((size_t)(b*T_FULL + 2*(rowblk*64 + rl)))*H_DIM + k];
    }
    __syncthreads();
    for (int idx = tid; idx < 2048; idx += 128) {
        int k = idx >> 5, rp = idx & 31;
        sa[k*32 + rp] = packf2(staged[2*rp][k], staged[2*rp+1][k]);
    }
    __syncthreads();

    const unsigned char* gsrc0 = (const unsigned char*)&g_bd[((size_t)(b*32 + jq*8))*2048];
    {
        unsigned sdst = (unsigned)__cvta_generic_to_shared(((unsigned char*)sbuf) + tid*16);
        #pragma unroll
        for (int i = 0; i < 8; i++)
            asm volatile("cp.async.cg.shared.global [%0], [%1], 16;"
                         :: "r"(sdst + i*2048), "l"(gsrc0 + tid*16 + i*2048));
        asm volatile("cp.async.commit_group;");
    }

    u64 acc[16];
    float rmax[16]; int rjdx[16];
    #pragma unroll
    for (int i = 0; i < 16; i++) { rmax[i] = -3.0e38f; rjdx[i] = 0; }

    for (int c = 0; c < 8; c++) {
        if (c + 1 < 8) {
            const unsigned char* gs = (const unsigned char*)&g_bd[((size_t)(b*32 + jq*8 + c + 1))*2048];
            unsigned sdst = (unsigned)__cvta_generic_to_shared(
                ((unsigned char*)sbuf) + (((c+1)&1)*16384) + tid*16);
            #pragma unroll
            for (int i = 0; i < 8; i++)
                asm volatile("cp.async.cg.shared.global [%0], [%1], 16;"
                             :: "r"(sdst + i*2048), "l"(gs + tid*16 + i*2048));
            asm volatile("cp.async.commit_group;");
            asm volatile("cp.async.wait_group 1;");
        } else {
            asm volatile("cp.async.wait_group 0;");
        }
        __syncthreads();

        int kc = c & 1;
        if (!kc) {
            #pragma unroll
            for (int i = 0; i < 16; i++) acc[i] = 0ULL;
        }
        const u64* bbase = sbuf + (c & 1)*2048 + 2*l;
        const u64* abase = sa + kc*1024 + 8*w;
        #pragma unroll 4
        for (int k32 = 0; k32 < 32; k32++) {
            ulonglong2 bq = *(const ulonglong2*)(bbase + k32*64);
            const u64* ar = abase + k32*32;
            ulonglong2 a0 = *(const ulonglong2*)(ar);
            ulonglong2 a1 = *(const ulonglong2*)(ar + 2);
            ulonglong2 a2 = *(const ulonglong2*)(ar + 4);
            ulonglong2 a3 = *(const ulonglong2*)(ar + 6);
            FMA2(acc[ 0], a0.x, bq.x); FMA2(acc[ 1], a0.x, bq.y);
            FMA2(acc[ 2], a0.y, bq.x); FMA2(acc[ 3], a0.y, bq.y);
            FMA2(acc[ 4], a1.x, bq.x); FMA2(acc[ 5], a1.x, bq.y);
            FMA2(acc[ 6], a1.y, bq.x); FMA2(acc[ 7], a1.y, bq.y);
            FMA2(acc[ 8], a2.x, bq.x); FMA2(acc[ 9], a2.x, bq.y);
            FMA2(acc[10], a2.y, bq.x); FMA2(acc[11], a2.y, bq.y);
            FMA2(acc[12], a3.x, bq.x); FMA2(acc[13], a3.x, bq.y);
            FMA2(acc[14], a3.y, bq.x); FMA2(acc[15], a3.y, bq.y);
        }
        if (kc) {
            int jb = jq*256 + (c >> 1)*64 + 2*l;
            #pragma unroll
            for (int rp = 0; rp < 8; rp++) {
                #pragma unroll
                for (int jj = 0; jj < 2; jj++) {
                    u64 a = acc[rp*2 + jj];
                    float lo = __uint_as_float((unsigned)(a & 0xffffffffu));
                    float hi = __uint_as_float((unsigned)(a >> 32));
                    int j = jb + jj;
                    if (lo > rmax[2*rp])   { rmax[2*rp]   = lo; rjdx[2*rp]   = j; }
                    if (hi > rmax[2*rp+1]) { rmax[2*rp+1] = hi; rjdx[2*rp+1] = j; }
                }
            }
        }
        __syncthreads();
    }

    int growbase = rowblk*64 + w*16;
    #pragma unroll
    for (int i = 0; i < 16; i++) {
        int grow = growbase + i;
        float inv = __ldg(&g_ainv[b*TA + grow]);
        u64 pk = ((u64)fflip(rmax[i]*inv) << 32) | (unsigned)(1023 - rjdx[i]);
        #pragma unroll
        for (int o = 16; o; o >>= 1) {
            u64 other = __shfl_down_sync(0xffffffffu, pk, o);
            if (other > pk) pk = other;
        }
        if (l == 0) atomicMax(&g_pack[b*TA + grow], pk);
    }
}

// ---------------- block exclusive scan (sum), 1024 threads ----------------
__device__ __forceinline__ unsigned block_exscan(unsigned v, unsigned* swarp,
                                                 int lane, int wid) {
    __syncthreads();
    unsigned inc = v;
    #pragma unroll
    for (int o = 1; o < 32; o <<= 1) {
        unsigned t = __shfl_up_sync(0xffffffffu, inc, o);
        if (lane >= o) inc += t;
    }
    if (lane == 31) swarp[wid] = inc;
    __syncthreads();
    if (wid == 0) {
        unsigned wv = swarp[lane];
        unsigned wi = wv;
        #pragma unroll
        for (int o = 1; o < 32; o <<= 1) {
            unsigned t = __shfl_up_sync(0xffffffffu, wi, o);
            if (lane >= o) wi += t;
        }
        swarp[lane] = wi - wv;
    }
    __syncthreads();
    return swarp[wid] + inc - v;
}

// ---------------- k_thresh: ONLY the 4-pass radix + per-batch equal counts (1 CTA) ----------------
__global__ void __launch_bounds__(1024) k_thresh() {
    __shared__ unsigned shist[256];
    __shared__ unsigned seq[BATCH];
    __shared__ unsigned s_prefix, s_kneed;
    int tid = threadIdx.x, lane = tid & 31, wid = tid >> 5;
    int base = tid * 8;

    unsigned uv[8];
    #pragma unroll
    for (int q = 0; q < 8; q++) uv[q] = (unsigned)(g_pack[base + q] >> 32);
    if (tid == 0) { s_prefix = 0u; s_kneed = RB; }
    if (tid < BATCH) seq[tid] = 0u;

    for (int byte = 3; byte >= 0; byte--) {
        int shift = byte * 8;
        unsigned maskhi = (byte == 3) ? 0u : (0xFFFFFFFFu << ((byte + 1) * 8));
        if (tid < 256) shist[tid] = 0u;
        __syncthreads();
        unsigned pref = s_prefix, kneed = s_kneed;
        #pragma unroll
        for (int q = 0; q < 8; q++) {
            unsigned u = uv[q];
            if ((u & maskhi) == pref) atomicAdd(&shist[(u >> shift) & 255u], 1u);
        }
        __syncthreads();
        if (wid == 0) {
            unsigned h[8]; unsigned cc = 0;
            int b0 = lane * 8;
            #pragma unroll
            for (int j = 0; j < 8; j++) { h[j] = shist[b0 + j]; cc += h[j]; }
            unsigned s = cc;
            #pragma unroll
            for (int o = 1; o < 32; o <<= 1) {
                unsigned t = __shfl_down_sync(0xffffffffu, s, o);
                if (lane + o < 32) s += t;
            }
            unsigned run = s - cc;
            #pragma unroll
            for (int j = 7; j >= 0; j--) { run += h[j]; shist[b0 + j] = run; }
        }
        __syncthreads();
        if (tid < 256) {
            unsigned S = shist[tid];
            unsigned above = (tid < 255) ? shist[tid + 1] : 0u;
            if (S >= kneed && above < kneed) {
                s_prefix = pref | ((unsigned)tid << shift);
                s_kneed  = kneed - above;
            }
        }
        __syncthreads();
    }
    unsigned thr = s_prefix;

    unsigned eq = 0;
    #pragma unroll
    for (int q = 0; q < 8; q++) eq += (uv[q] == thr);
    if (eq) atomicAdd(&seq[tid >> 7], eq);
    __syncthreads();
    if (tid == 0) {
        unsigned run = 0;
        #pragma unroll
        for (int b2 = 0; b2 < BATCH; b2++) { g_eqbase[b2] = run; run += seq[b2]; }
        g_thr = thr; g_kprime = s_kneed;
    }
}

// ---------------- k_plan: per-batch flags + plan table + merge lists (8 CTAs) ----------------
__global__ void __launch_bounds__(1024) k_plan() {
    __shared__ unsigned swarp[32];
    __shared__ unsigned cnt[1024];
    __shared__ unsigned s_mb;
    int b = blockIdx.x, tid = threadIdx.x, lane = tid & 31, wid = tid >> 5;
    int i = b*TA + tid;

    u64 p = g_pack[i];
    g_pack[i] = 0ULL;                       // reset for next replay (atomicMax combine)
    unsigned key = (unsigned)(p >> 32);
    int j = 1023 - (int)(p & 0xffffffffu);

    unsigned thr = g_thr, kprime = g_kprime, eqb = g_eqbase[b];
    unsigned eq = (key == thr) ? 1u : 0u;
    unsigned er = block_exscan(eq, swarp, lane, wid);
    int flag = (key > thr) || (eq && (eqb + er) < kprime);

    unsigned rank_m = block_exscan((unsigned)flag, swarp, lane, wid);
    if (tid == 1023) s_mb = rank_m + (unsigned)flag;
    __syncthreads();
    int mb = (int)s_mb;

    int* tab = g_table + b * T_FULL;
    if (flag) tab[2048 - mb + (int)rank_m] = -1;
    else      tab[tid - (int)rank_m] = 2 * tid;
    tab[(1024 - mb) + tid] = 2 * tid + 1;

    cnt[tid] = 0u;
    __syncthreads();
    if (flag) atomicAdd(&cnt[j], 1u);
    __syncthreads();
    unsigned c = cnt[tid];
    unsigned off = block_exscan(c, swarp, lane, wid);
    g_dstoff[b*TB + tid] = b*1024 + (int)off;
    g_dstdeg[b*TB + tid] = (int)c;
    __syncthreads();
    cnt[tid] = off;
    __syncthreads();
    if (flag) {
        unsigned pos = atomicAdd(&cnt[j], 1u);
        g_dstlist[b*1024 + pos] = i;
    }
}

// ---------------- final gather/divide + size_s + pad_s (R5-proven simple loop) ----------------
__global__ void __launch_bounds__(256) k_out(const float* __restrict__ x,
                                             const float* __restrict__ size,
                                             float* __restrict__ out) {
    int row = blockIdx.x;
    int b = row >> 11;
    int tid = threadIdx.x;
    int code = g_table[row];
    float4* orow = reinterpret_cast<float4*>(out + (size_t)row*C_DIM);

    if (code < 0) {
        __stcs(&orow[tid], make_float4(0.f,0.f,0.f,0.f));
        if (tid == 0) { out[X_ELEMS + row] = 0.f; out[X_ELEMS + BATCH*T_FULL + row] = 1.f; }
        return;
    }
    const float4* xrow = reinterpret_cast<const float4*>(x + ((size_t)(b*T_FULL + code))*C_DIM);
    float sv = size[b*T_FULL + code];
    float4 v = __ldcs(&xrow[tid]);
    float4 acc; acc.x = v.x*sv; acc.y = v.y*sv; acc.z = v.z*sv; acc.w = v.w*sv;
    float ssum = sv;
    if (code & 1) {
        int d = b*TB + (code >> 1);
        int off = g_dstoff[d], deg = g_dstdeg[d];
        for (int e = 0; e < deg; e++) {
            int si = g_dstlist[off + e];
            int srow = (si >> 10)*T_FULL + 2*(si & 1023);
            float ssv = size[srow];
            const float4* sx = reinterpret_cast<const float4*>(x + (size_t)srow*C_DIM);
            float4 a = __ldcs(&sx[tid]);
            acc.x += a.x*ssv; acc.y += a.y*ssv; acc.z += a.z*ssv; acc.w += a.w*ssv;
            ssum += ssv;
        }
    }
    float invd = 1.0f / (ssum + 1e-4f);
    float4 r; r.x = acc.x*invd; r.y = acc.y*invd; r.z = acc.z*invd; r.w = acc.w*invd;
    __stcs(&orow[tid], r);
    if (tid == 0) { out[X_ELEMS + row] = ssum; out[X_ELEMS + BATCH*T_FULL + row] = 0.f; }
}

// ---------------- launch ----------------
extern "C" void kernel_launch(void* const* d_in, const int* in_sizes, int n_in,
                              void* d_out, int out_size) {
    const float* x      = (const float*)d_in[0];
    const float* metric = (const float*)d_in[1];
    const float* size   = (const float*)d_in[2];
    float* out = (float*)d_out;
    (void)in_sizes; (void)n_in; (void)out_size;

    k_prep<<<dim3(16, 8), 256>>>(metric);
    k_scores<<<dim3(16, 4, 8), 128>>>(metric);
    k_thresh<<<1, 1024>>>();
    k_plan<<<BATCH, 1024>>>();
    k_out<<<BATCH*T_FULL, 256>>>(x, size, out);
}

// round 17
// speedup vs baseline: 1.0511x; 1.0511x over previous
#include <cuda_runtime.h>
#include <cstdint>

#define BATCH 8
#define T_FULL 2048
#define C_DIM 1024
#define H_DIM 64
#define TA 1024
#define TB 1024
#define R_MERGE 512
#define RB (R_MERGE*BATCH)   /* 4096 */
#define NROWS (BATCH*TA)     /* 8192 */
#define X_ELEMS (BATCH*T_FULL*C_DIM)  /* 16777216 */

typedef unsigned long long u64;

// ---------------- scratch (__device__ globals; zero-initialized .bss) ----------------
__device__ u64 g_pack[NROWS];                  // (flip(max)<<32)|(1023-argmax); reset by k_plan
__device__ int g_table[BATCH*T_FULL];
__device__ int g_dstoff[NROWS];
__device__ int g_dstdeg[NROWS];
__device__ int g_dstlist[NROWS];               // per-batch segmented: batch b owns [b*1024, b*1024+mb)
__device__ unsigned g_thr, g_kprime;
__device__ unsigned g_eqbase[BATCH];
// normalized-b, duplicated (v,v) f32x2, chunked: [b][chunk32][k32][j64]
__device__ __align__(16) u64 g_bd[BATCH*32*32*64];   // 4 MB
__device__ float g_ainv[NROWS];                // 1/||a_row||

__device__ __forceinline__ unsigned fflip(float f) {
    unsigned u = __float_as_uint(f);
    return (u & 0x80000000u) ? ~u : (u | 0x80000000u);
}
__device__ __forceinline__ u64 packf2(float lo, float hi) {
    u64 r; asm("mov.b64 %0, {%1,%2};" : "=l"(r) : "f"(lo), "f"(hi)); return r;
}
#define FMA2(acc, av, bv) asm("fma.rn.f32x2 %0, %1, %2, %0;" : "+l"(acc) : "l"(av), "l"(bv))

// ---------------- prep: normalize b tokens (dup layout) + a-row inverse norms ----------------
__global__ void __launch_bounds__(256) k_prep(const float* __restrict__ metric) {
    __shared__ float st[64][65];
    int jt = blockIdx.x;          // 0..15 (64-token tiles)
    int b  = blockIdx.y;
    int tid = threadIdx.x, lane = tid & 31, w = tid >> 5;

    for (int r = w*8; r < w*8 + 8; r++) {
        int row = jt*64 + r;
        const float* m = metric + ((size_t)(b*T_FULL + 2*row))*H_DIM;
        float v0 = m[lane], v1 = m[lane+32];
        float ss = v0*v0 + v1*v1;
        #pragma unroll
        for (int o = 16; o; o >>= 1) ss += __shfl_xor_sync(0xffffffffu, ss, o);
        if (lane == 0) g_ainv[b*TA + row] = 1.0f / sqrtf(ss);
    }

    for (int idx = tid; idx < 64*64; idx += 256) {
        int t = idx >> 6, k = idx & 63;
        st[t][k] = metric[((size_t)(b*T_FULL + 2*(jt*64 + t) + 1))*H_DIM + k];
    }
    __syncthreads();
    for (int t = w*8; t < w*8 + 8; t++) {
        float v0 = st[t][lane], v1 = st[t][lane+32];
        float ss = v0*v0 + v1*v1;
        #pragma unroll
        for (int o = 16; o; o >>= 1) ss += __shfl_xor_sync(0xffffffffu, ss, o);
        float inv = 1.0f / sqrtf(ss);
        st[t][lane] = v0*inv; st[t][lane+32] = v1*inv;
    }
    __syncthreads();
    for (int idx = tid; idx < 4096; idx += 256) {
        int kc = idx >> 11, k32 = (idx >> 6) & 31, jl = idx & 63;
        float v = st[jl][kc*32 + k32];
        g_bd[(((size_t)(b*32 + jt*2 + kc))*32 + k32)*64 + jl] = packf2(v, v);
    }
}

// ---------------- scores: 16 rows/warp x 64 j, cp.async double-buffered (R15-proven) ----------------
__global__ void __launch_bounds__(128) k_scores(const float* __restrict__ metric) {
    __shared__ __align__(16) unsigned char smem_raw[49152];
    u64* sa   = (u64*)smem_raw;                        // [64k][32rp] 16KB
    u64* sbuf = (u64*)(smem_raw + 16384);              // 2 x 16KB b chunks
    float (*staged)[65] = (float(*)[65])(smem_raw + 16384);  // prologue only

    int rowblk = blockIdx.x;     // 0..15 (64 rows)
    int jhalf  = blockIdx.y;     // 0..1
    int b      = blockIdx.z;     // 0..7
    int tid = threadIdx.x, l = tid & 31, w = tid >> 5;

    for (int idx = tid; idx < 64*64; idx += 128) {
        int rl = idx >> 6, k = idx & 63;
        staged[rl][k] = metric[((size_t)(b*T_FULL + 2*(rowblk*64 + rl)))*H_DIM + k];
    }
    __syncthreads();
    for (int idx = tid; idx < 2048; idx += 128) {
        int k = idx >> 5, rp = idx & 31;
        sa[k*32 + rp] = packf2(staged[2*rp][k], staged[2*rp+1][k]);
    }
    __syncthreads();

    const unsigned char* gsrc0 = (const unsigned char*)&g_bd[((size_t)(b*32 + jhalf*16))*2048];
    {
        unsigned sdst = (unsigned)__cvta_generic_to_shared(((unsigned char*)sbuf) + tid*16);
        #pragma unroll
        for (int i = 0; i < 8; i++)
            asm volatile("cp.async.cg.shared.global [%0], [%1], 16;"
                         :: "r"(sdst + i*2048), "l"(gsrc0 + tid*16 + i*2048));
        asm volatile("cp.async.commit_group;");
    }

    u64 acc[16];
    float rmax[16]; int rjdx[16];
    #pragma unroll
    for (int i = 0; i < 16; i++) { rmax[i] = -3.0e38f; rjdx[i] = 0; }

    for (int c = 0; c < 16; c++) {
        if (c + 1 < 16) {
            const unsigned char* gs = (const unsigned char*)&g_bd[((size_t)(b*32 + jhalf*16 + c + 1))*2048];
            unsigned sdst = (unsigned)__cvta_generic_to_shared(
                ((unsigned char*)sbuf) + (((c+1)&1)*16384) + tid*16);
            #pragma unroll
            for (int i = 0; i < 8; i++)
                asm volatile("cp.async.cg.shared.global [%0], [%1], 16;"
                             :: "r"(sdst + i*2048), "l"(gs + tid*16 + i*2048));
            asm volatile("cp.async.commit_group;");
            asm volatile("cp.async.wait_group 1;");
        } else {
            asm volatile("cp.async.wait_group 0;");
        }
        __syncthreads();

        int kc = c & 1;
        if (!kc) {
            #pragma unroll
            for (int i = 0; i < 16; i++) acc[i] = 0ULL;
        }
        const u64* bbase = sbuf + (c & 1)*2048 + 2*l;
        const u64* abase = sa + kc*1024 + 8*w;
        #pragma unroll 4
        for (int k32 = 0; k32 < 32; k32++) {
            ulonglong2 bq = *(const ulonglong2*)(bbase + k32*64);
            const u64* ar = abase + k32*32;
            ulonglong2 a0 = *(const ulonglong2*)(ar);
            ulonglong2 a1 = *(const ulonglong2*)(ar + 2);
            ulonglong2 a2 = *(const ulonglong2*)(ar + 4);
            ulonglong2 a3 = *(const ulonglong2*)(ar + 6);
            FMA2(acc[ 0], a0.x, bq.x); FMA2(acc[ 1], a0.x, bq.y);
            FMA2(acc[ 2], a0.y, bq.x); FMA2(acc[ 3], a0.y, bq.y);
            FMA2(acc[ 4], a1.x, bq.x); FMA2(acc[ 5], a1.x, bq.y);
            FMA2(acc[ 6], a1.y, bq.x); FMA2(acc[ 7], a1.y, bq.y);
            FMA2(acc[ 8], a2.x, bq.x); FMA2(acc[ 9], a2.x, bq.y);
            FMA2(acc[10], a2.y, bq.x); FMA2(acc[11], a2.y, bq.y);
            FMA2(acc[12], a3.x, bq.x); FMA2(acc[13], a3.x, bq.y);
            FMA2(acc[14], a3.y, bq.x); FMA2(acc[15], a3.y, bq.y);
        }
        if (kc) {
            int jb = jhalf*512 + (c >> 1)*64 + 2*l;
            #pragma unroll
            for (int rp = 0; rp < 8; rp++) {
                #pragma unroll
                for (int jj = 0; jj < 2; jj++) {
                    u64 a = acc[rp*2 + jj];
                    float lo = __uint_as_float((unsigned)(a & 0xffffffffu));
                    float hi = __uint_as_float((unsigned)(a >> 32));
                    int j = jb + jj;
                    if (lo > rmax[2*rp])   { rmax[2*rp]   = lo; rjdx[2*rp]   = j; }
                    if (hi > rmax[2*rp+1]) { rmax[2*rp+1] = hi; rjdx[2*rp+1] = j; }
                }
            }
        }
        __syncthreads();
    }

    int growbase = rowblk*64 + w*16;
    #pragma unroll
    for (int i = 0; i < 16; i++) {
        int grow = growbase + i;
        float inv = __ldg(&g_ainv[b*TA + grow]);
        u64 pk = ((u64)fflip(rmax[i]*inv) << 32) | (unsigned)(1023 - rjdx[i]);
        #pragma unroll
        for (int o = 16; o; o >>= 1) {
            u64 other = __shfl_down_sync(0xffffffffu, pk, o);
            if (other > pk) pk = other;
        }
        if (l == 0) atomicMax(&g_pack[b*TA + grow], pk);
    }
}

// ---------------- block exclusive scan (sum), 1024 threads ----------------
__device__ __forceinline__ unsigned block_exscan(unsigned v, unsigned* swarp,
                                                 int lane, int wid) {
    __syncthreads();
    unsigned inc = v;
    #pragma unroll
    for (int o = 1; o < 32; o <<= 1) {
        unsigned t = __shfl_up_sync(0xffffffffu, inc, o);
        if (lane >= o) inc += t;
    }
    if (lane == 31) swarp[wid] = inc;
    __syncthreads();
    if (wid == 0) {
        unsigned wv = swarp[lane];
        unsigned wi = wv;
        #pragma unroll
        for (int o = 1; o < 32; o <<= 1) {
            unsigned t = __shfl_up_sync(0xffffffffu, wi, o);
            if (lane >= o) wi += t;
        }
        swarp[lane] = wi - wv;
    }
    __syncthreads();
    return swarp[wid] + inc - v;
}

// ---------------- k_thresh: 4-pass radix + per-batch equal counts (1 CTA) ----------------
__global__ void __launch_bounds__(1024) k_thresh() {
    __shared__ unsigned shist[256];
    __shared__ unsigned seq[BATCH];
    __shared__ unsigned s_prefix, s_kneed;
    int tid = threadIdx.x, lane = tid & 31, wid = tid >> 5;
    int base = tid * 8;

    unsigned uv[8];
    #pragma unroll
    for (int q = 0; q < 8; q++) uv[q] = (unsigned)(g_pack[base + q] >> 32);
    if (tid == 0) { s_prefix = 0u; s_kneed = RB; }
    if (tid < BATCH) seq[tid] = 0u;

    for (int byte = 3; byte >= 0; byte--) {
        int shift = byte * 8;
        unsigned maskhi = (byte == 3) ? 0u : (0xFFFFFFFFu << ((byte + 1) * 8));
        if (tid < 256) shist[tid] = 0u;
        __syncthreads();
        unsigned pref = s_prefix, kneed = s_kneed;
        #pragma unroll
        for (int q = 0; q < 8; q++) {
            unsigned u = uv[q];
            if ((u & maskhi) == pref) atomicAdd(&shist[(u >> shift) & 255u], 1u);
        }
        __syncthreads();
        if (wid == 0) {
            unsigned h[8]; unsigned cc = 0;
            int b0 = lane * 8;
            #pragma unroll
            for (int j = 0; j < 8; j++) { h[j] = shist[b0 + j]; cc += h[j]; }
            unsigned s = cc;
            #pragma unroll
            for (int o = 1; o < 32; o <<= 1) {
                unsigned t = __shfl_down_sync(0xffffffffu, s, o);
                if (lane + o < 32) s += t;
            }
            unsigned run = s - cc;
            #pragma unroll
            for (int j = 7; j >= 0; j--) { run += h[j]; shist[b0 + j] = run; }
        }
        __syncthreads();
        if (tid < 256) {
            unsigned S = shist[tid];
            unsigned above = (tid < 255) ? shist[tid + 1] : 0u;
            if (S >= kneed && above < kneed) {
                s_prefix = pref | ((unsigned)tid << shift);
                s_kneed  = kneed - above;
            }
        }
        __syncthreads();
    }
    unsigned thr = s_prefix;

    unsigned eq = 0;
    #pragma unroll
    for (int q = 0; q < 8; q++) eq += (uv[q] == thr);
    if (eq) atomicAdd(&seq[tid >> 7], eq);
    __syncthreads();
    if (tid == 0) {
        unsigned run = 0;
        #pragma unroll
        for (int b2 = 0; b2 < BATCH; b2++) { g_eqbase[b2] = run; run += seq[b2]; }
        g_thr = thr; g_kprime = s_kneed;
    }
}

// ---------------- k_plan: per-batch flags + plan table + merge lists (8 CTAs) ----------------
__global__ void __launch_bounds__(1024) k_plan() {
    __shared__ unsigned swarp[32];
    __shared__ unsigned cnt[1024];
    __shared__ unsigned s_mb;
    int b = blockIdx.x, tid = threadIdx.x, lane = tid & 31, wid = tid >> 5;
    int i = b*TA + tid;

    u64 p = g_pack[i];
    g_pack[i] = 0ULL;                       // reset for next replay (atomicMax combine)
    unsigned key = (unsigned)(p >> 32);
    int j = 1023 - (int)(p & 0xffffffffu);

    unsigned thr = g_thr, kprime = g_kprime, eqb = g_eqbase[b];
    unsigned eq = (key == thr) ? 1u : 0u;
    unsigned er = block_exscan(eq, swarp, lane, wid);
    int flag = (key > thr) || (eq && (eqb + er) < kprime);

    unsigned rank_m = block_exscan((unsigned)flag, swarp, lane, wid);
    if (tid == 1023) s_mb = rank_m + (unsigned)flag;
    __syncthreads();
    int mb = (int)s_mb;

    int* tab = g_table + b * T_FULL;
    if (flag) tab[2048 - mb + (int)rank_m] = -1;
    else      tab[tid - (int)rank_m] = 2 * tid;
    tab[(1024 - mb) + tid] = 2 * tid + 1;

    cnt[tid] = 0u;
    __syncthreads();
    if (flag) atomicAdd(&cnt[j], 1u);
    __syncthreads();
    unsigned c = cnt[tid];
    unsigned off = block_exscan(c, swarp, lane, wid);
    g_dstoff[b*TB + tid] = b*1024 + (int)off;
    g_dstdeg[b*TB + tid] = (int)c;
    __syncthreads();
    cnt[tid] = off;
    __syncthreads();
    if (flag) {
        unsigned pos = atomicAdd(&cnt[j], 1u);
        g_dstlist[b*1024 + pos] = i;
    }
}

// ---------------- final gather/divide: 2 rows/CTA, 2 float4/thread (MLP=2) ----------------
__global__ void __launch_bounds__(256) k_out(const float* __restrict__ x,
                                             const float* __restrict__ size,
                                             float* __restrict__ out) {
    int row = blockIdx.x*2 + (threadIdx.x >> 7);   // 2 rows per CTA, 128 threads each
    int t   = threadIdx.x & 127;                   // float4 index base within row
    int b = row >> 11;
    int code = g_table[row];
    float4* orow = reinterpret_cast<float4*>(out + (size_t)row*C_DIM);

    if (code < 0) {                     // merged tail slot: zeros, size 0, pad 1
        float4 z = make_float4(0.f,0.f,0.f,0.f);
        __stcs(&orow[t], z);
        __stcs(&orow[t+128], z);
        if (t == 0) { out[X_ELEMS + row] = 0.f; out[X_ELEMS + BATCH*T_FULL + row] = 1.f; }
        return;
    }
    const float4* xrow = reinterpret_cast<const float4*>(x + ((size_t)(b*T_FULL + code))*C_DIM);
    float sv = size[b*T_FULL + code];
    float4 v0 = __ldcs(&xrow[t]);
    float4 v1 = __ldcs(&xrow[t+128]);
    float4 a0, a1;
    a0.x = v0.x*sv; a0.y = v0.y*sv; a0.z = v0.z*sv; a0.w = v0.w*sv;
    a1.x = v1.x*sv; a1.y = v1.y*sv; a1.z = v1.z*sv; a1.w = v1.w*sv;
    float ssum = sv;
    if (code & 1) {                     // dst row: gather merged srcs
        int d = b*TB + (code >> 1);
        int off = g_dstoff[d], deg = g_dstdeg[d];
        for (int e = 0; e < deg; e++) {
            int si = g_dstlist[off + e];
            int srow = (si >> 10)*T_FULL + 2*(si & 1023);
            float ssv = size[srow];
            const float4* sx = reinterpret_cast<const float4*>(x + (size_t)srow*C_DIM);
            float4 g0 = __ldcs(&sx[t]);
            float4 g1 = __ldcs(&sx[t+128]);
            a0.x += g0.x*ssv; a0.y += g0.y*ssv; a0.z += g0.z*ssv; a0.w += g0.w*ssv;
            a1.x += g1.x*ssv; a1.y += g1.y*ssv; a1.z += g1.z*ssv; a1.w += g1.w*ssv;
            ssum += ssv;
        }
    }
    float invd = 1.0f / (ssum + 1e-4f);
    float4 r0, r1;
    r0.x = a0.x*invd; r0.y = a0.y*invd; r0.z = a0.z*invd; r0.w = a0.w*invd;
    r1.x = a1.x*invd; r1.y = a1.y*invd; r1.z = a1.z*invd; r1.w = a1.w*invd;
    __stcs(&orow[t], r0);
    __stcs(&orow[t+128], r1);
    if (t == 0) { out[X_ELEMS + row] = ssum; out[X_ELEMS + BATCH*T_FULL + row] = 0.f; }
}

// ---------------- launch ----------------
extern "C" void kernel_launch(void* const* d_in, const int* in_sizes, int n_in,
                              void* d_out, int out_size) {
    const float* x      = (const float*)d_in[0];
    const float* metric = (const float*)d_in[1];
    const float* size   = (const float*)d_in[2];
    float* out = (float*)d_out;
    (void)in_sizes; (void)n_in; (void)out_size;

    k_prep<<<dim3(16, 8), 256>>>(metric);
    k_scores<<<dim3(16, 2, 8), 128>>>(metric);
    k_thresh<<<1, 1024>>>();
    k_plan<<<BATCH, 1024>>>();
    k_out<<<BATCH*T_FULL/2, 256>>>(x, size, out);
}